// round 16
// baseline (speedup 1.0000x reference)
#include <cuda_runtime.h>
#include <cuda_fp16.h>
#include <cstdint>
#include <math.h>

#define BATCH 8
#define NN    2048
#define DD    256
#define MT    (BATCH * NN)
#define G3    (3 * DD)

// ---------------------------------------------------------------------------
// Scratch (device globals)
// ---------------------------------------------------------------------------
__device__ __align__(16) __half g_xh  [MT * DD];
__device__ __align__(16) __half g_xnh [MT * DD];
__device__ __align__(16) __half g_W16 [DD * DD];
__device__ __align__(16) __half g_Wihh[G3 * DD];
__device__ __align__(16) __half g_Whhh[G3 * DD];
__device__ __align__(16) __half g_WhO [MT * DD];
__device__ __align__(16) __half g_go  [MT * DD];
__device__ __align__(16) __half g_gi  [MT * G3];
__device__ __align__(16) __half g_gh  [MT * G3];
__device__ __align__(16) uint32_t g_adjbits[(size_t)MT * 64];

// ---------------------------------------------------------------------------
// PTX helpers (sm_75/80-era only)
// ---------------------------------------------------------------------------
__device__ __forceinline__ uint32_t s2u(const void* p) {
    uint32_t a;
    asm("{ .reg .u64 t; cvta.to.shared.u64 t, %1; cvt.u32.u64 %0, t; }" : "=r"(a) : "l"(p));
    return a;
}
__device__ __forceinline__ void cp16(uint32_t dst, const void* src) {
    asm volatile("cp.async.cg.shared.global [%0], [%1], 16;" :: "r"(dst), "l"(src));
}
__device__ __forceinline__ void cp8(uint32_t dst, const void* src) {
    asm volatile("cp.async.ca.shared.global [%0], [%1], 8;" :: "r"(dst), "l"(src));
}
__device__ __forceinline__ void ldsm4(uint32_t& r0, uint32_t& r1, uint32_t& r2, uint32_t& r3,
                                      uint32_t a) {
    asm volatile("ldmatrix.sync.aligned.m8n8.x4.shared.b16 {%0,%1,%2,%3}, [%4];"
                 : "=r"(r0), "=r"(r1), "=r"(r2), "=r"(r3) : "r"(a));
}
__device__ __forceinline__ void ldsm4t(uint32_t& r0, uint32_t& r1, uint32_t& r2, uint32_t& r3,
                                       uint32_t a) {
    asm volatile("ldmatrix.sync.aligned.m8n8.x4.trans.shared.b16 {%0,%1,%2,%3}, [%4];"
                 : "=r"(r0), "=r"(r1), "=r"(r2), "=r"(r3) : "r"(a));
}
__device__ __forceinline__ void mma16(float& c0, float& c1, float& c2, float& c3,
                                      uint32_t a0, uint32_t a1, uint32_t a2, uint32_t a3,
                                      uint32_t b0, uint32_t b1) {
    asm volatile(
        "mma.sync.aligned.m16n8k16.row.col.f32.f16.f16.f32 "
        "{%0,%1,%2,%3}, {%4,%5,%6,%7}, {%8,%9}, {%0,%1,%2,%3};"
        : "+f"(c0), "+f"(c1), "+f"(c2), "+f"(c3)
        : "r"(a0), "r"(a1), "r"(a2), "r"(a3), "r"(b0), "r"(b1));
}

// ===========================================================================
// adj -> bitmask pack (vectorized int4 + bit-spread repack)
// g_adjbits[row][w] bit c = (adj[row][32w+c] > 0)
// ===========================================================================
__device__ __forceinline__ uint32_t bitspread(uint32_t x) {
    x = (x | (x << 12)) & 0x000F000Fu;
    x = (x | (x << 6))  & 0x03030303u;
    x = (x | (x << 3))  & 0x11111111u;
    return x;  // bit i -> bit 4i
}

__global__ __launch_bounds__(256) void k_pack(const int* __restrict__ adj)
{
    int row = blockIdx.x * 8 + (threadIdx.x >> 5);
    int lane = threadIdx.x & 31;
    const int4* r = (const int4*)(adj + (size_t)row * NN);
    uint32_t* o = g_adjbits + (size_t)row * 64;
#pragma unroll 4
    for (int w = 0; w < 16; w++) {          // 16 chunks of 128 cols
        int4 v = r[w * 32 + lane];          // lane covers cols 128w+4*lane..+3
        uint32_t b0 = __ballot_sync(0xffffffffu, v.x > 0);
        uint32_t b1 = __ballot_sync(0xffffffffu, v.y > 0);
        uint32_t b2 = __ballot_sync(0xffffffffu, v.z > 0);
        uint32_t b3 = __ballot_sync(0xffffffffu, v.w > 0);
        if (lane < 4) {
            uint32_t e0 = (b0 >> (8 * lane)) & 0xFFu;
            uint32_t e1 = (b1 >> (8 * lane)) & 0xFFu;
            uint32_t e2 = (b2 >> (8 * lane)) & 0xFFu;
            uint32_t e3 = (b3 >> (8 * lane)) & 0xFFu;
            o[w * 4 + lane] = bitspread(e0) | (bitspread(e1) << 1)
                            | (bitspread(e2) << 2) | (bitspread(e3) << 3);
        }
    }
}

// ===========================================================================
// Fused attention, FA2-style register-resident P (byte-identical to R15)
// ===========================================================================
#define SMEM_ATT 198656

__global__ void __launch_bounds__(256, 1)
k_attn(const __half* __restrict__ xnh_g, const __half* __restrict__ Wh_g,
       const uint32_t* __restrict__ bitsg, __half* __restrict__ go_g)
{
    extern __shared__ __align__(16) char smdyn[];
    const uint32_t smu = s2u(smdyn);
    const uint32_t Qb = smu, K0 = smu + 65536u, Wh0 = smu + 131072u, Bt0 = smu + 196608u;
    const int tid = threadIdx.x, lane = tid & 31, wid = tid >> 5;
    const int rw = wid * 16;
    const int b = blockIdx.y;
    const size_t rowBase = (size_t)blockIdx.x * 128;
    const __half* Xb = xnh_g + (size_t)b * NN * DD;
    const __half* Vb = Wh_g  + (size_t)b * NN * DD;
    const int gr = lane >> 2, gc2 = (lane & 3) * 2;

    auto load_K = [&](int j, int s) {
        size_t colBase = (size_t)j * 64;
        uint32_t dst = K0 + (uint32_t)s * 32768u;
#pragma unroll
        for (int i = 0; i < 8; i++) {
            int c = tid + i * 256;
            int n = c >> 5, ch = c & 31;
            cp16(dst + (uint32_t)(n * 512 + ((ch ^ (n & 7)) << 4)),
                 Xb + (colBase + n) * DD + ch * 8);
        }
    };
    auto load_Wh = [&](int j, int s) {
        size_t colBase = (size_t)j * 64;
        uint32_t dst = Wh0 + (uint32_t)s * 32768u;
#pragma unroll
        for (int i = 0; i < 8; i++) {
            int c = tid + i * 256;
            int k = c >> 5, ch = c & 31;
            cp16(dst + (uint32_t)(k * 512 + ((ch ^ (k & 7)) << 4)),
                 Vb + (colBase + k) * DD + ch * 8);
        }
    };
    auto load_bits = [&](int j, int s) {
        if (tid < 128)
            cp8(Bt0 + (uint32_t)s * 1024u + (uint32_t)tid * 8,
                bitsg + ((size_t)b * NN + rowBase + tid) * 64 + j * 2);
    };

#pragma unroll
    for (int i = 0; i < 16; i++) {
        int c = tid + i * 256;
        int row = c >> 5, ch = c & 31;
        cp16(Qb + (uint32_t)(row * 512 + ((ch ^ (row & 7)) << 4)),
             Xb + (rowBase + row) * DD + ch * 8);
    }
    load_K(0, 0); load_Wh(0, 0); load_bits(0, 0);
    asm volatile("cp.async.commit_group;");

    float acc_o[32][4];
#pragma unroll
    for (int t = 0; t < 32; t++)
#pragma unroll
        for (int q = 0; q < 4; q++) acc_o[t][q] = 0.f;
    float rs0 = 0.f, rs1 = 0.f;

    for (int j = 0; j < 32; j++) {
        const int s = j & 1;
        if (j + 1 < 32) {
            load_K(j + 1, s ^ 1); load_Wh(j + 1, s ^ 1); load_bits(j + 1, s ^ 1);
        }
        asm volatile("cp.async.commit_group;");
        asm volatile("cp.async.wait_group 1;");
        __syncthreads();

        const uint32_t Kb  = K0  + (uint32_t)s * 32768u;
        const uint32_t Whb = Wh0 + (uint32_t)s * 32768u;
        const uint32_t Btb = Bt0 + (uint32_t)s * 1024u;

        float acc_s[8][4];
#pragma unroll
        for (int ni = 0; ni < 8; ni++)
#pragma unroll
            for (int q = 0; q < 4; q++) acc_s[ni][q] = 0.f;
#pragma unroll
        for (int ks = 0; ks < 16; ks++) {
            const int ch0 = 2 * ks + (lane >> 4);
            uint32_t af[4], bf[8][2];
            {
                int rr = rw + (lane & 15);
                ldsm4(af[0], af[1], af[2], af[3],
                      Qb + (uint32_t)(rr * 512 + ((ch0 ^ (rr & 7)) << 4)));
            }
#pragma unroll
            for (int p = 0; p < 4; p++) {
                int n = p * 16 + (lane & 15);
                ldsm4(bf[2 * p][0], bf[2 * p + 1][0], bf[2 * p][1], bf[2 * p + 1][1],
                      Kb + (uint32_t)(n * 512 + ((ch0 ^ (n & 7)) << 4)));
            }
#pragma unroll
            for (int ni = 0; ni < 8; ni++)
                mma16(acc_s[ni][0], acc_s[ni][1], acc_s[ni][2], acc_s[ni][3],
                      af[0], af[1], af[2], af[3], bf[ni][0], bf[ni][1]);
        }

        uint32_t ph0[8], ph1[8];
        {
            int r0l = rw + gr, r1l = r0l + 8;
            uint32_t w00 = *(const uint32_t*)(smdyn + (Btb - smu) + r0l * 8);
            uint32_t w01 = *(const uint32_t*)(smdyn + (Btb - smu) + r0l * 8 + 4);
            uint32_t w10 = *(const uint32_t*)(smdyn + (Btb - smu) + r1l * 8);
            uint32_t w11 = *(const uint32_t*)(smdyn + (Btb - smu) + r1l * 8 + 4);
#pragma unroll
            for (int ni = 0; ni < 8; ni++) {
                int col = 8 * ni + gc2;
                uint32_t wa = (ni < 4) ? w00 : w01;
                uint32_t wb = (ni < 4) ? w10 : w11;
                int bp = col & 31;
                float v0 = ((wa >> bp) & 1u)       ? __expf(acc_s[ni][0]) : 0.f;
                float v1 = ((wa >> (bp + 1)) & 1u) ? __expf(acc_s[ni][1]) : 0.f;
                float v2 = ((wb >> bp) & 1u)       ? __expf(acc_s[ni][2]) : 0.f;
                float v3 = ((wb >> (bp + 1)) & 1u) ? __expf(acc_s[ni][3]) : 0.f;
                __half2 h0 = __floats2half2_rn(v0, v1);
                __half2 h1 = __floats2half2_rn(v2, v3);
                ph0[ni] = *(uint32_t*)&h0;
                ph1[ni] = *(uint32_t*)&h1;
                rs0 += __low2float(h0) + __high2float(h0);
                rs1 += __low2float(h1) + __high2float(h1);
            }
        }

#pragma unroll
        for (int kc = 0; kc < 4; kc++) {
            uint32_t a0 = ph0[2 * kc], a1 = ph1[2 * kc];
            uint32_t a2 = ph0[2 * kc + 1], a3 = ph1[2 * kc + 1];
            const int kl = kc * 16 + (lane & 7) + (((lane >> 3) & 1) << 3);
#pragma unroll
            for (int t = 0; t < 16; t++) {
                int chn = 2 * t + (lane >> 4);
                uint32_t b0l, b0h, b1l, b1h;
                ldsm4t(b0l, b0h, b1l, b1h,
                       Whb + (uint32_t)(kl * 512 + ((chn ^ (kl & 7)) << 4)));
                mma16(acc_o[2 * t][0], acc_o[2 * t][1], acc_o[2 * t][2], acc_o[2 * t][3],
                      a0, a1, a2, a3, b0l, b0h);
                mma16(acc_o[2 * t + 1][0], acc_o[2 * t + 1][1],
                      acc_o[2 * t + 1][2], acc_o[2 * t + 1][3],
                      a0, a1, a2, a3, b1l, b1h);
            }
        }
        __syncthreads();
    }
    asm volatile("cp.async.wait_group 0;");

    rs0 += __shfl_xor_sync(0xffffffffu, rs0, 1);
    rs0 += __shfl_xor_sync(0xffffffffu, rs0, 2);
    rs1 += __shfl_xor_sync(0xffffffffu, rs1, 1);
    rs1 += __shfl_xor_sync(0xffffffffu, rs1, 2);
    float inv0 = 1.f / rs0, inv1 = 1.f / rs1;

    {
        int r0l = rw + gr, r1l = r0l + 8;
        __half* o0 = go_g + ((size_t)b * NN + rowBase + r0l) * DD;
        __half* o1 = go_g + ((size_t)b * NN + rowBase + r1l) * DD;
#pragma unroll
        for (int t = 0; t < 32; t++) {
            int cc = 8 * t + gc2;
            *(__half2*)(o0 + cc) = __floats2half2_rn(acc_o[t][0] * inv0,
                                                     acc_o[t][1] * inv0);
            *(__half2*)(o1 + cc) = __floats2half2_rn(acc_o[t][2] * inv1,
                                                     acc_o[t][3] * inv1);
        }
    }
}

// ---------------------------------------------------------------------------
// fp16 mma.sync GEMM: block 128x128, 8 warps (64x32), K-chunk 128 (2 chunks),
// double-buffered. Stage pitch 256B (16 chunks), swizzle ch^(row&7).
// MODE 0: Wh = x@W (NN). MODE 3: lin = A@Wt^T + bias (NT).
// ---------------------------------------------------------------------------
#define SMEM_TOTAL 131072

template <int MODE>
__global__ void __launch_bounds__(256)
gemm_h(const __half* __restrict__ A, const __half* __restrict__ B,
       __half* __restrict__ Cb, const float* __restrict__ bias,
       int K, int lda, int ldb, int ldc)
{
    constexpr bool BT = (MODE == 3);
    extern __shared__ __align__(16) char smdyn[];
    const uint32_t smu = s2u(smdyn);

    const int tid = threadIdx.x, lane = tid & 31, wid = tid >> 5;
    const int wm = (wid & 1) * 64, wn = (wid >> 1) * 32;
    const size_t rowBase = (size_t)blockIdx.y * 128;
    const size_t colBase = (size_t)blockIdx.x * 128;

    auto load_stage = [&](int s, int k0) {
        uint32_t da = smu + (uint32_t)s * 32768u;
#pragma unroll
        for (int i = 0; i < 8; i++) {
            int c = tid + i * 256;
            int row = c >> 4, ch = c & 15;
            cp16(da + (uint32_t)(row * 256 + ((ch ^ (row & 7)) << 4)),
                 A + (rowBase + row) * (size_t)lda + k0 + ch * 8);
        }
        uint32_t db = smu + 65536u + (uint32_t)s * 32768u;
        if (BT) {
#pragma unroll
            for (int i = 0; i < 8; i++) {
                int c = tid + i * 256;
                int row = c >> 4, ch = c & 15;
                cp16(db + (uint32_t)(row * 256 + ((ch ^ (row & 7)) << 4)),
                     B + (colBase + row) * (size_t)ldb + k0 + ch * 8);
            }
        } else {
#pragma unroll
            for (int i = 0; i < 8; i++) {
                int c = tid + i * 256;
                int row = c >> 4, ch = c & 15;
                cp16(db + (uint32_t)(row * 256 + ((ch ^ (row & 7)) << 4)),
                     B + (size_t)(k0 + row) * ldb + colBase + ch * 8);
            }
        }
    };

    float acc[4][4][4];
#pragma unroll
    for (int mi = 0; mi < 4; mi++)
#pragma unroll
        for (int ni = 0; ni < 4; ni++)
#pragma unroll
            for (int j = 0; j < 4; j++) acc[mi][ni][j] = 0.f;

    load_stage(0, 0);
    asm volatile("cp.async.commit_group;");
    const int NCk = K / 128;
    for (int c = 0; c < NCk; c++) {
        if (c + 1 < NCk) load_stage((c + 1) & 1, (c + 1) * 128);
        asm volatile("cp.async.commit_group;");
        asm volatile("cp.async.wait_group 1;");
        __syncthreads();
        const uint32_t aB = smu + (uint32_t)(c & 1) * 32768u;
        const uint32_t bB = smu + 65536u + (uint32_t)(c & 1) * 32768u;
#pragma unroll
        for (int ks = 0; ks < 8; ks++) {
            uint32_t af[4][4], bf[4][2];
            {
                const int r0 = wm + (lane & 15);
                const int ch0 = 2 * ks + (lane >> 4);
#pragma unroll
                for (int mi = 0; mi < 4; mi++) {
                    int rr = r0 + mi * 16;
                    ldsm4(af[mi][0], af[mi][1], af[mi][2], af[mi][3],
                          aB + (uint32_t)(rr * 256 + ((ch0 ^ (rr & 7)) << 4)));
                }
            }
            if (BT) {
                const int n0 = wn + (lane & 15);
                const int ch = 2 * ks + (lane >> 4);
#pragma unroll
                for (int p = 0; p < 2; p++) {
                    int n = n0 + p * 16;
                    ldsm4(bf[2 * p][0], bf[2 * p + 1][0], bf[2 * p][1], bf[2 * p + 1][1],
                          bB + (uint32_t)(n * 256 + ((ch ^ (n & 7)) << 4)));
                }
            } else {
                const int k = ks * 16 + (lane & 7) + (((lane >> 3) & 1) << 3);
#pragma unroll
                for (int p = 0; p < 2; p++) {
                    int chn = ((wn + p * 16) >> 3) + (lane >> 4);
                    ldsm4t(bf[2 * p][0], bf[2 * p][1], bf[2 * p + 1][0], bf[2 * p + 1][1],
                           bB + (uint32_t)(k * 256 + ((chn ^ (k & 7)) << 4)));
                }
            }
#pragma unroll
            for (int mi = 0; mi < 4; mi++)
#pragma unroll
                for (int ni = 0; ni < 4; ni++)
                    mma16(acc[mi][ni][0], acc[mi][ni][1], acc[mi][ni][2], acc[mi][ni][3],
                          af[mi][0], af[mi][1], af[mi][2], af[mi][3],
                          bf[ni][0], bf[ni][1]);
        }
        __syncthreads();
    }

    const int gr = lane >> 2, gc2 = (lane & 3) * 2;
#pragma unroll
    for (int mi = 0; mi < 4; mi++) {
        size_t r0 = rowBase + wm + mi * 16 + gr;
        size_t r1 = r0 + 8;
#pragma unroll
        for (int ni = 0; ni < 4; ni++) {
            size_t cc = colBase + wn + ni * 8 + gc2;
            float v0 = acc[mi][ni][0], v1 = acc[mi][ni][1];
            float v2 = acc[mi][ni][2], v3 = acc[mi][ni][3];
            if (MODE == 3) {
                float b0 = bias[cc], b1 = bias[cc + 1];
                v0 += b0; v1 += b1; v2 += b0; v3 += b1;
            }
            *(__half2*)(Cb + r0 * (size_t)ldc + cc) = __floats2half2_rn(v0, v1);
            *(__half2*)(Cb + r1 * (size_t)ldc + cc) = __floats2half2_rn(v2, v3);
        }
    }
}

// ---------------------------------------------------------------------------
// Elementwise kernels
// ---------------------------------------------------------------------------
#define N4_X   (MT * DD / 4)
#define N4_W   (DD * DD / 4)
#define N4_WG  (G3 * DD / 4)
#define N4_TOT (N4_X + N4_W + 2 * N4_WG)

__global__ __launch_bounds__(256) void k_conv(const float* __restrict__ x,
                                              const float* __restrict__ W,
                                              const float* __restrict__ Wih_,
                                              const float* __restrict__ Whh_)
{
    int i = blockIdx.x * 256 + threadIdx.x;
    if (i >= N4_TOT) return;
    const float* s;
    __half* d;
    int k;
    if (i < N4_X)                    { s = x;    d = g_xh;   k = i; }
    else if (i < N4_X + N4_W)        { s = W;    d = g_W16;  k = i - N4_X; }
    else if (i < N4_X + N4_W + N4_WG){ s = Wih_; d = g_Wihh; k = i - N4_X - N4_W; }
    else                             { s = Whh_; d = g_Whhh; k = i - N4_X - N4_W - N4_WG; }
    float4 v = ((const float4*)s)[k];
    __half2 a = __floats2half2_rn(v.x, v.y);
    __half2 b2 = __floats2half2_rn(v.z, v.w);
    uint2 o;
    o.x = *(uint32_t*)&a;
    o.y = *(uint32_t*)&b2;
    ((uint2*)d)[k] = o;
}

__global__ __launch_bounds__(256) void k_norm(const float* __restrict__ xt)
{
    int row = blockIdx.x * 8 + (threadIdx.x >> 5);
    int lane = threadIdx.x & 31;
    const float4* src = (const float4*)(xt + (size_t)row * DD);
    float4 v0 = src[lane];
    float4 v1 = src[lane + 32];
    float s = v0.x * v0.x + v0.y * v0.y + v0.z * v0.z + v0.w * v0.w
            + v1.x * v1.x + v1.y * v1.y + v1.z * v1.z + v1.w * v1.w;
#pragma unroll
    for (int o = 16; o > 0; o >>= 1) s += __shfl_xor_sync(0xffffffffu, s, o);
    float inv = rsqrtf(fmaxf(s, 1e-30f));
    __half2 a0 = __floats2half2_rn(v0.x * inv, v0.y * inv);
    __half2 a1 = __floats2half2_rn(v0.z * inv, v0.w * inv);
    __half2 b0 = __floats2half2_rn(v1.x * inv, v1.y * inv);
    __half2 b1 = __floats2half2_rn(v1.z * inv, v1.w * inv);
    uint2* dst = (uint2*)(g_xnh + (size_t)row * DD);
    uint2 oa; oa.x = *(uint32_t*)&a0; oa.y = *(uint32_t*)&a1;
    uint2 ob; ob.x = *(uint32_t*)&b0; ob.y = *(uint32_t*)&b1;
    dst[lane] = oa;
    dst[lane + 32] = ob;
}

__global__ __launch_bounds__(128) void k_gate(const float* __restrict__ x,
                                              float* __restrict__ out)
{
    size_t row = blockIdx.x;
    int d2 = threadIdx.x * 2;
    const __half* gi = g_gi + row * G3;
    const __half* gh = g_gh + row * G3;
    __half2 ir = *(const __half2*)(gi + d2);
    __half2 hr = *(const __half2*)(gh + d2);
    __half2 iz = *(const __half2*)(gi + DD + d2);
    __half2 hz = *(const __half2*)(gh + DD + d2);
    __half2 in_ = *(const __half2*)(gi + 2 * DD + d2);
    __half2 hn = *(const __half2*)(gh + 2 * DD + d2);
    float2 xv = *(const float2*)(x + row * DD + d2);
    float r0 = 1.f / (1.f + __expf(-(__low2float(ir) + __low2float(hr))));
    float r1 = 1.f / (1.f + __expf(-(__high2float(ir) + __high2float(hr))));
    float z0 = 1.f / (1.f + __expf(-(__low2float(iz) + __low2float(hz))));
    float z1 = 1.f / (1.f + __expf(-(__high2float(iz) + __high2float(hz))));
    float n0 = tanhf(__low2float(in_) + r0 * __low2float(hn));
    float n1 = tanhf(__high2float(in_) + r1 * __high2float(hn));
    float2 o;
    o.x = (1.f - z0) * n0 + z0 * xv.x;
    o.y = (1.f - z1) * n1 + z1 * xv.y;
    *(float2*)(out + row * DD + d2) = o;
}

// ---------------------------------------------------------------------------
// Launch — parallel-DAG graph: pack (sB), norm (sN), gh (sC) overlapped.
// ---------------------------------------------------------------------------
extern "C" void kernel_launch(void* const* d_in, const int* in_sizes, int n_in,
                              void* d_out, int out_size)
{
    const int*   adj  = (const int*)  d_in[0];
    const float* x    = (const float*)d_in[1];
    const float* xt   = (const float*)d_in[2];
    const float* W    = (const float*)d_in[3];
    const float* W_ih = (const float*)d_in[4];
    const float* W_hh = (const float*)d_in[5];
    const float* b_ih = (const float*)d_in[6];
    const float* b_hh = (const float*)d_in[7];
    float* out = (float*)d_out;

    static bool init_done = []() {
        cudaFuncSetAttribute(gemm_h<0>, cudaFuncAttributeMaxDynamicSharedMemorySize, SMEM_TOTAL);
        cudaFuncSetAttribute(gemm_h<3>, cudaFuncAttributeMaxDynamicSharedMemorySize, SMEM_TOTAL);
        cudaFuncSetAttribute(k_attn,    cudaFuncAttributeMaxDynamicSharedMemorySize, SMEM_ATT);
        return true;
    }();
    (void)init_done;

    static cudaStream_t sB = []() {
        cudaStream_t s; cudaStreamCreateWithFlags(&s, cudaStreamNonBlocking); return s;
    }();
    static cudaStream_t sC = []() {
        cudaStream_t s; cudaStreamCreateWithFlags(&s, cudaStreamNonBlocking); return s;
    }();
    static cudaStream_t sN = []() {
        cudaStream_t s; cudaStreamCreateWithFlags(&s, cudaStreamNonBlocking); return s;
    }();
    static cudaEvent_t e0 = []() {
        cudaEvent_t e; cudaEventCreateWithFlags(&e, cudaEventDisableTiming); return e;
    }();
    static cudaEvent_t e1 = []() {
        cudaEvent_t e; cudaEventCreateWithFlags(&e, cudaEventDisableTiming); return e;
    }();
    static cudaEvent_t eB = []() {
        cudaEvent_t e; cudaEventCreateWithFlags(&e, cudaEventDisableTiming); return e;
    }();
    static cudaEvent_t eC = []() {
        cudaEvent_t e; cudaEventCreateWithFlags(&e, cudaEventDisableTiming); return e;
    }();
    static cudaEvent_t eN = []() {
        cudaEvent_t e; cudaEventCreateWithFlags(&e, cudaEventDisableTiming); return e;
    }();

    __half* xh  = nullptr; cudaGetSymbolAddress((void**)&xh,  g_xh);
    __half* xnh = nullptr; cudaGetSymbolAddress((void**)&xnh, g_xnh);
    __half* W16 = nullptr; cudaGetSymbolAddress((void**)&W16, g_W16);
    __half* Wih = nullptr; cudaGetSymbolAddress((void**)&Wih, g_Wihh);
    __half* Whh = nullptr; cudaGetSymbolAddress((void**)&Whh, g_Whhh);
    __half* WhO = nullptr; cudaGetSymbolAddress((void**)&WhO, g_WhO);
    __half* go  = nullptr; cudaGetSymbolAddress((void**)&go,  g_go);
    __half* gi  = nullptr; cudaGetSymbolAddress((void**)&gi,  g_gi);
    __half* gh  = nullptr; cudaGetSymbolAddress((void**)&gh,  g_gh);
    uint32_t* bits = nullptr; cudaGetSymbolAddress((void**)&bits, g_adjbits);

    // fork at t0: pack (adj only) and norm (xt only)
    cudaEventRecord(e0, 0);
    cudaStreamWaitEvent(sB, e0, 0);
    k_pack<<<MT / 8, 256, 0, sB>>>(adj);
    cudaEventRecord(eB, sB);
    cudaStreamWaitEvent(sN, e0, 0);
    k_norm<<<MT / 8, 256, 0, sN>>>(xt);
    cudaEventRecord(eN, sN);

    k_conv<<<(N4_TOT + 255) / 256, 256>>>(x, W, W_ih, W_hh);

    // fork C: gh = x @ W_hh^T + b_hh (needs conv only)
    cudaEventRecord(e1, 0);
    cudaStreamWaitEvent(sC, e1, 0);
    gemm_h<3><<<dim3(G3 / 128, MT / 128, 1), 256, SMEM_TOTAL, sC>>>(
        xh, Whh, gh, b_hh, DD, DD, DD, G3);
    cudaEventRecord(eC, sC);

    // main: Wh gemm, then attention (joins pack + norm)
    gemm_h<0><<<dim3(DD / 128, MT / 128, 1), 256, SMEM_TOTAL>>>(
        xh, W16, WhO, nullptr, DD, DD, DD, DD);
    cudaStreamWaitEvent(0, eB, 0);
    cudaStreamWaitEvent(0, eN, 0);
    k_attn<<<dim3(NN / 128, BATCH), 256, SMEM_ATT>>>(xnh, WhO, bits, go);

    gemm_h<3><<<dim3(G3 / 128, MT / 128, 1), 256, SMEM_TOTAL>>>(
        go, Wih, gi, b_ih, DD, DD, DD, G3);

    cudaStreamWaitEvent(0, eC, 0);
    k_gate<<<MT, 128>>>(x, out);
}

// round 17
// speedup vs baseline: 1.0417x; 1.0417x over previous
#include <cuda_runtime.h>
#include <cuda_fp16.h>
#include <cstdint>
#include <math.h>

#define BATCH 8
#define NN    2048
#define DD    256
#define MT    (BATCH * NN)
#define G3    (3 * DD)

// ---------------------------------------------------------------------------
// Scratch (device globals)
// ---------------------------------------------------------------------------
__device__ __align__(16) __half g_xh  [MT * DD];
__device__ __align__(16) __half g_xnh [MT * DD];
__device__ __align__(16) __half g_W16 [DD * DD];
__device__ __align__(16) __half g_Wihh[G3 * DD];
__device__ __align__(16) __half g_Whhh[G3 * DD];
__device__ __align__(16) __half g_WhO [MT * DD];
__device__ __align__(16) __half g_go  [MT * DD];
__device__ __align__(16) __half g_gi  [MT * G3];
__device__ __align__(16) __half g_gh  [MT * G3];
__device__ __align__(16) uint32_t g_adjbits[(size_t)MT * 64];

// ---------------------------------------------------------------------------
// PTX helpers (sm_75/80-era only)
// ---------------------------------------------------------------------------
__device__ __forceinline__ uint32_t s2u(const void* p) {
    uint32_t a;
    asm("{ .reg .u64 t; cvta.to.shared.u64 t, %1; cvt.u32.u64 %0, t; }" : "=r"(a) : "l"(p));
    return a;
}
__device__ __forceinline__ void cp16(uint32_t dst, const void* src) {
    asm volatile("cp.async.cg.shared.global [%0], [%1], 16;" :: "r"(dst), "l"(src));
}
__device__ __forceinline__ void cp8(uint32_t dst, const void* src) {
    asm volatile("cp.async.ca.shared.global [%0], [%1], 8;" :: "r"(dst), "l"(src));
}
__device__ __forceinline__ void ldsm4(uint32_t& r0, uint32_t& r1, uint32_t& r2, uint32_t& r3,
                                      uint32_t a) {
    asm volatile("ldmatrix.sync.aligned.m8n8.x4.shared.b16 {%0,%1,%2,%3}, [%4];"
                 : "=r"(r0), "=r"(r1), "=r"(r2), "=r"(r3) : "r"(a));
}
__device__ __forceinline__ void ldsm4t(uint32_t& r0, uint32_t& r1, uint32_t& r2, uint32_t& r3,
                                       uint32_t a) {
    asm volatile("ldmatrix.sync.aligned.m8n8.x4.trans.shared.b16 {%0,%1,%2,%3}, [%4];"
                 : "=r"(r0), "=r"(r1), "=r"(r2), "=r"(r3) : "r"(a));
}
__device__ __forceinline__ void mma16(float& c0, float& c1, float& c2, float& c3,
                                      uint32_t a0, uint32_t a1, uint32_t a2, uint32_t a3,
                                      uint32_t b0, uint32_t b1) {
    asm volatile(
        "mma.sync.aligned.m16n8k16.row.col.f32.f16.f16.f32 "
        "{%0,%1,%2,%3}, {%4,%5,%6,%7}, {%8,%9}, {%0,%1,%2,%3};"
        : "+f"(c0), "+f"(c1), "+f"(c2), "+f"(c3)
        : "r"(a0), "r"(a1), "r"(a2), "r"(a3), "r"(b0), "r"(b1));
}

// ===========================================================================
// adj -> bitmask pack (vectorized int4 + bit-spread repack)
// ===========================================================================
__device__ __forceinline__ uint32_t bitspread(uint32_t x) {
    x = (x | (x << 12)) & 0x000F000Fu;
    x = (x | (x << 6))  & 0x03030303u;
    x = (x | (x << 3))  & 0x11111111u;
    return x;
}

__global__ __launch_bounds__(256) void k_pack(const int* __restrict__ adj)
{
    int row = blockIdx.x * 8 + (threadIdx.x >> 5);
    int lane = threadIdx.x & 31;
    const int4* r = (const int4*)(adj + (size_t)row * NN);
    uint32_t* o = g_adjbits + (size_t)row * 64;
#pragma unroll 4
    for (int w = 0; w < 16; w++) {
        int4 v = r[w * 32 + lane];
        uint32_t b0 = __ballot_sync(0xffffffffu, v.x > 0);
        uint32_t b1 = __ballot_sync(0xffffffffu, v.y > 0);
        uint32_t b2 = __ballot_sync(0xffffffffu, v.z > 0);
        uint32_t b3 = __ballot_sync(0xffffffffu, v.w > 0);
        if (lane < 4) {
            uint32_t e0 = (b0 >> (8 * lane)) & 0xFFu;
            uint32_t e1 = (b1 >> (8 * lane)) & 0xFFu;
            uint32_t e2 = (b2 >> (8 * lane)) & 0xFFu;
            uint32_t e3 = (b3 >> (8 * lane)) & 0xFFu;
            o[w * 4 + lane] = bitspread(e0) | (bitspread(e1) << 1)
                            | (bitspread(e2) << 2) | (bitspread(e3) << 3);
        }
    }
}

// ===========================================================================
// Fused attention, FA2-style register-resident P (byte-identical to R15 best)
// ===========================================================================
#define SMEM_ATT 198656

__global__ void __launch_bounds__(256, 1)
k_attn(const __half* __restrict__ xnh_g, const __half* __restrict__ Wh_g,
       const uint32_t* __restrict__ bitsg, __half* __restrict__ go_g)
{
    extern __shared__ __align__(16) char smdyn[];
    const uint32_t smu = s2u(smdyn);
    const uint32_t Qb = smu, K0 = smu + 65536u, Wh0 = smu + 131072u, Bt0 = smu + 196608u;
    const int tid = threadIdx.x, lane = tid & 31, wid = tid >> 5;
    const int rw = wid * 16;
    const int b = blockIdx.y;
    const size_t rowBase = (size_t)blockIdx.x * 128;
    const __half* Xb = xnh_g + (size_t)b * NN * DD;
    const __half* Vb = Wh_g  + (size_t)b * NN * DD;
    const int gr = lane >> 2, gc2 = (lane & 3) * 2;

    auto load_K = [&](int j, int s) {
        size_t colBase = (size_t)j * 64;
        uint32_t dst = K0 + (uint32_t)s * 32768u;
#pragma unroll
        for (int i = 0; i < 8; i++) {
            int c = tid + i * 256;
            int n = c >> 5, ch = c & 31;
            cp16(dst + (uint32_t)(n * 512 + ((ch ^ (n & 7)) << 4)),
                 Xb + (colBase + n) * DD + ch * 8);
        }
    };
    auto load_Wh = [&](int j, int s) {
        size_t colBase = (size_t)j * 64;
        uint32_t dst = Wh0 + (uint32_t)s * 32768u;
#pragma unroll
        for (int i = 0; i < 8; i++) {
            int c = tid + i * 256;
            int k = c >> 5, ch = c & 31;
            cp16(dst + (uint32_t)(k * 512 + ((ch ^ (k & 7)) << 4)),
                 Vb + (colBase + k) * DD + ch * 8);
        }
    };
    auto load_bits = [&](int j, int s) {
        if (tid < 128)
            cp8(Bt0 + (uint32_t)s * 1024u + (uint32_t)tid * 8,
                bitsg + ((size_t)b * NN + rowBase + tid) * 64 + j * 2);
    };

#pragma unroll
    for (int i = 0; i < 16; i++) {
        int c = tid + i * 256;
        int row = c >> 5, ch = c & 31;
        cp16(Qb + (uint32_t)(row * 512 + ((ch ^ (row & 7)) << 4)),
             Xb + (rowBase + row) * DD + ch * 8);
    }
    load_K(0, 0); load_Wh(0, 0); load_bits(0, 0);
    asm volatile("cp.async.commit_group;");

    float acc_o[32][4];
#pragma unroll
    for (int t = 0; t < 32; t++)
#pragma unroll
        for (int q = 0; q < 4; q++) acc_o[t][q] = 0.f;
    float rs0 = 0.f, rs1 = 0.f;

    for (int j = 0; j < 32; j++) {
        const int s = j & 1;
        if (j + 1 < 32) {
            load_K(j + 1, s ^ 1); load_Wh(j + 1, s ^ 1); load_bits(j + 1, s ^ 1);
        }
        asm volatile("cp.async.commit_group;");
        asm volatile("cp.async.wait_group 1;");
        __syncthreads();

        const uint32_t Kb  = K0  + (uint32_t)s * 32768u;
        const uint32_t Whb = Wh0 + (uint32_t)s * 32768u;
        const uint32_t Btb = Bt0 + (uint32_t)s * 1024u;

        float acc_s[8][4];
#pragma unroll
        for (int ni = 0; ni < 8; ni++)
#pragma unroll
            for (int q = 0; q < 4; q++) acc_s[ni][q] = 0.f;
#pragma unroll
        for (int ks = 0; ks < 16; ks++) {
            const int ch0 = 2 * ks + (lane >> 4);
            uint32_t af[4], bf[8][2];
            {
                int rr = rw + (lane & 15);
                ldsm4(af[0], af[1], af[2], af[3],
                      Qb + (uint32_t)(rr * 512 + ((ch0 ^ (rr & 7)) << 4)));
            }
#pragma unroll
            for (int p = 0; p < 4; p++) {
                int n = p * 16 + (lane & 15);
                ldsm4(bf[2 * p][0], bf[2 * p + 1][0], bf[2 * p][1], bf[2 * p + 1][1],
                      Kb + (uint32_t)(n * 512 + ((ch0 ^ (n & 7)) << 4)));
            }
#pragma unroll
            for (int ni = 0; ni < 8; ni++)
                mma16(acc_s[ni][0], acc_s[ni][1], acc_s[ni][2], acc_s[ni][3],
                      af[0], af[1], af[2], af[3], bf[ni][0], bf[ni][1]);
        }

        uint32_t ph0[8], ph1[8];
        {
            int r0l = rw + gr, r1l = r0l + 8;
            uint32_t w00 = *(const uint32_t*)(smdyn + (Btb - smu) + r0l * 8);
            uint32_t w01 = *(const uint32_t*)(smdyn + (Btb - smu) + r0l * 8 + 4);
            uint32_t w10 = *(const uint32_t*)(smdyn + (Btb - smu) + r1l * 8);
            uint32_t w11 = *(const uint32_t*)(smdyn + (Btb - smu) + r1l * 8 + 4);
#pragma unroll
            for (int ni = 0; ni < 8; ni++) {
                int col = 8 * ni + gc2;
                uint32_t wa = (ni < 4) ? w00 : w01;
                uint32_t wb = (ni < 4) ? w10 : w11;
                int bp = col & 31;
                float v0 = ((wa >> bp) & 1u)       ? __expf(acc_s[ni][0]) : 0.f;
                float v1 = ((wa >> (bp + 1)) & 1u) ? __expf(acc_s[ni][1]) : 0.f;
                float v2 = ((wb >> bp) & 1u)       ? __expf(acc_s[ni][2]) : 0.f;
                float v3 = ((wb >> (bp + 1)) & 1u) ? __expf(acc_s[ni][3]) : 0.f;
                __half2 h0 = __floats2half2_rn(v0, v1);
                __half2 h1 = __floats2half2_rn(v2, v3);
                ph0[ni] = *(uint32_t*)&h0;
                ph1[ni] = *(uint32_t*)&h1;
                rs0 += __low2float(h0) + __high2float(h0);
                rs1 += __low2float(h1) + __high2float(h1);
            }
        }

#pragma unroll
        for (int kc = 0; kc < 4; kc++) {
            uint32_t a0 = ph0[2 * kc], a1 = ph1[2 * kc];
            uint32_t a2 = ph0[2 * kc + 1], a3 = ph1[2 * kc + 1];
            const int kl = kc * 16 + (lane & 7) + (((lane >> 3) & 1) << 3);
#pragma unroll
            for (int t = 0; t < 16; t++) {
                int chn = 2 * t + (lane >> 4);
                uint32_t b0l, b0h, b1l, b1h;
                ldsm4t(b0l, b0h, b1l, b1h,
                       Whb + (uint32_t)(kl * 512 + ((chn ^ (kl & 7)) << 4)));
                mma16(acc_o[2 * t][0], acc_o[2 * t][1], acc_o[2 * t][2], acc_o[2 * t][3],
                      a0, a1, a2, a3, b0l, b0h);
                mma16(acc_o[2 * t + 1][0], acc_o[2 * t + 1][1],
                      acc_o[2 * t + 1][2], acc_o[2 * t + 1][3],
                      a0, a1, a2, a3, b1l, b1h);
            }
        }
        __syncthreads();
    }
    asm volatile("cp.async.wait_group 0;");

    rs0 += __shfl_xor_sync(0xffffffffu, rs0, 1);
    rs0 += __shfl_xor_sync(0xffffffffu, rs0, 2);
    rs1 += __shfl_xor_sync(0xffffffffu, rs1, 1);
    rs1 += __shfl_xor_sync(0xffffffffu, rs1, 2);
    float inv0 = 1.f / rs0, inv1 = 1.f / rs1;

    {
        int r0l = rw + gr, r1l = r0l + 8;
        __half* o0 = go_g + ((size_t)b * NN + rowBase + r0l) * DD;
        __half* o1 = go_g + ((size_t)b * NN + rowBase + r1l) * DD;
#pragma unroll
        for (int t = 0; t < 32; t++) {
            int cc = 8 * t + gc2;
            *(__half2*)(o0 + cc) = __floats2half2_rn(acc_o[t][0] * inv0,
                                                     acc_o[t][1] * inv0);
            *(__half2*)(o1 + cc) = __floats2half2_rn(acc_o[t][2] * inv1,
                                                     acc_o[t][3] * inv1);
        }
    }
}

// ---------------------------------------------------------------------------
// fp16 mma.sync GEMM (exact R15 config): block 128x128, 8 warps (64x32),
// K-chunk 64, 64 KB smem, 2-CTA occupancy hint.
// MODE 0: Wh = x@W (NN). MODE 3: lin = A@Wt^T + bias (NT).
// ---------------------------------------------------------------------------
#define SMEM_TOTAL 65536

template <int MODE>
__global__ void __launch_bounds__(256, 2)
gemm_h(const __half* __restrict__ A, const __half* __restrict__ B,
       __half* __restrict__ Cb, const float* __restrict__ bias,
       int K, int lda, int ldb, int ldc)
{
    constexpr bool BT = (MODE == 3);
    extern __shared__ __align__(16) char smdyn[];
    const uint32_t smu = s2u(smdyn);

    const int tid = threadIdx.x, lane = tid & 31, wid = tid >> 5;
    const int wm = (wid & 1) * 64, wn = (wid >> 1) * 32;
    const size_t rowBase = (size_t)blockIdx.y * 128;
    const size_t colBase = (size_t)blockIdx.x * 128;

    auto load_stage = [&](int s, int k0) {
        uint32_t da = smu + (uint32_t)s * 16384u;
#pragma unroll
        for (int i = 0; i < 4; i++) {
            int c = tid + i * 256;
            int row = c >> 3, ch = c & 7;
            cp16(da + (uint32_t)(row * 128 + ((ch ^ (row & 7)) << 4)),
                 A + (rowBase + row) * (size_t)lda + k0 + ch * 8);
        }
        uint32_t db = smu + 32768u + (uint32_t)s * 16384u;
        if (BT) {
#pragma unroll
            for (int i = 0; i < 4; i++) {
                int c = tid + i * 256;
                int row = c >> 3, ch = c & 7;
                cp16(db + (uint32_t)(row * 128 + ((ch ^ (row & 7)) << 4)),
                     B + (colBase + row) * (size_t)ldb + k0 + ch * 8);
            }
        } else {
#pragma unroll
            for (int i = 0; i < 4; i++) {
                int c = tid + i * 256;
                int row = c >> 4, ch = c & 15;
                cp16(db + (uint32_t)(row * 256 + ((ch ^ (row & 7)) << 4)),
                     B + (size_t)(k0 + row) * ldb + colBase + ch * 8);
            }
        }
    };

    float acc[4][4][4];
#pragma unroll
    for (int mi = 0; mi < 4; mi++)
#pragma unroll
        for (int ni = 0; ni < 4; ni++)
#pragma unroll
            for (int j = 0; j < 4; j++) acc[mi][ni][j] = 0.f;

    load_stage(0, 0);
    asm volatile("cp.async.commit_group;");
    const int NCk = K / 64;
    for (int c = 0; c < NCk; c++) {
        if (c + 1 < NCk) load_stage((c + 1) & 1, (c + 1) * 64);
        asm volatile("cp.async.commit_group;");
        asm volatile("cp.async.wait_group 1;");
        __syncthreads();
        const uint32_t aB = smu + (uint32_t)(c & 1) * 16384u;
        const uint32_t bB = smu + 32768u + (uint32_t)(c & 1) * 16384u;
#pragma unroll
        for (int ks = 0; ks < 4; ks++) {
            uint32_t af[4][4], bf[4][2];
            {
                const int r0 = wm + (lane & 15);
                const int ch0 = 2 * ks + (lane >> 4);
#pragma unroll
                for (int mi = 0; mi < 4; mi++) {
                    int rr = r0 + mi * 16;
                    ldsm4(af[mi][0], af[mi][1], af[mi][2], af[mi][3],
                          aB + (uint32_t)(rr * 128 + ((ch0 ^ (rr & 7)) << 4)));
                }
            }
            if (BT) {
                const int n0 = wn + (lane & 15);
                const int ch = 2 * ks + (lane >> 4);
#pragma unroll
                for (int p = 0; p < 2; p++) {
                    int n = n0 + p * 16;
                    ldsm4(bf[2 * p][0], bf[2 * p + 1][0], bf[2 * p][1], bf[2 * p + 1][1],
                          bB + (uint32_t)(n * 128 + ((ch ^ (n & 7)) << 4)));
                }
            } else {
                const int k = ks * 16 + (lane & 7) + (((lane >> 3) & 1) << 3);
#pragma unroll
                for (int p = 0; p < 2; p++) {
                    int chn = ((wn + p * 16) >> 3) + (lane >> 4);
                    ldsm4t(bf[2 * p][0], bf[2 * p][1], bf[2 * p + 1][0], bf[2 * p + 1][1],
                           bB + (uint32_t)(k * 256 + ((chn ^ (k & 7)) << 4)));
                }
            }
#pragma unroll
            for (int mi = 0; mi < 4; mi++)
#pragma unroll
                for (int ni = 0; ni < 4; ni++)
                    mma16(acc[mi][ni][0], acc[mi][ni][1], acc[mi][ni][2], acc[mi][ni][3],
                          af[mi][0], af[mi][1], af[mi][2], af[mi][3],
                          bf[ni][0], bf[ni][1]);
        }
        __syncthreads();
    }

    const int gr = lane >> 2, gc2 = (lane & 3) * 2;
#pragma unroll
    for (int mi = 0; mi < 4; mi++) {
        size_t r0 = rowBase + wm + mi * 16 + gr;
        size_t r1 = r0 + 8;
#pragma unroll
        for (int ni = 0; ni < 4; ni++) {
            size_t cc = colBase + wn + ni * 8 + gc2;
            float v0 = acc[mi][ni][0], v1 = acc[mi][ni][1];
            float v2 = acc[mi][ni][2], v3 = acc[mi][ni][3];
            if (MODE == 3) {
                float b0 = bias[cc], b1 = bias[cc + 1];
                v0 += b0; v1 += b1; v2 += b0; v3 += b1;
            }
            *(__half2*)(Cb + r0 * (size_t)ldc + cc) = __floats2half2_rn(v0, v1);
            *(__half2*)(Cb + r1 * (size_t)ldc + cc) = __floats2half2_rn(v2, v3);
        }
    }
}

// ---------------------------------------------------------------------------
// Elementwise kernels
// ---------------------------------------------------------------------------
#define N4_X   (MT * DD / 4)
#define N4_W   (DD * DD / 4)
#define N4_WG  (G3 * DD / 4)
#define N4_TOT (N4_X + N4_W + 2 * N4_WG)

__global__ __launch_bounds__(256) void k_conv(const float* __restrict__ x,
                                              const float* __restrict__ W,
                                              const float* __restrict__ Wih_,
                                              const float* __restrict__ Whh_)
{
    int i = blockIdx.x * 256 + threadIdx.x;
    if (i >= N4_TOT) return;
    const float* s;
    __half* d;
    int k;
    if (i < N4_X)                    { s = x;    d = g_xh;   k = i; }
    else if (i < N4_X + N4_W)        { s = W;    d = g_W16;  k = i - N4_X; }
    else if (i < N4_X + N4_W + N4_WG){ s = Wih_; d = g_Wihh; k = i - N4_X - N4_W; }
    else                             { s = Whh_; d = g_Whhh; k = i - N4_X - N4_W - N4_WG; }
    float4 v = ((const float4*)s)[k];
    __half2 a = __floats2half2_rn(v.x, v.y);
    __half2 b2 = __floats2half2_rn(v.z, v.w);
    uint2 o;
    o.x = *(uint32_t*)&a;
    o.y = *(uint32_t*)&b2;
    ((uint2*)d)[k] = o;
}

__global__ __launch_bounds__(256) void k_norm(const float* __restrict__ xt)
{
    int row = blockIdx.x * 8 + (threadIdx.x >> 5);
    int lane = threadIdx.x & 31;
    const float4* src = (const float4*)(xt + (size_t)row * DD);
    float4 v0 = src[lane];
    float4 v1 = src[lane + 32];
    float s = v0.x * v0.x + v0.y * v0.y + v0.z * v0.z + v0.w * v0.w
            + v1.x * v1.x + v1.y * v1.y + v1.z * v1.z + v1.w * v1.w;
#pragma unroll
    for (int o = 16; o > 0; o >>= 1) s += __shfl_xor_sync(0xffffffffu, s, o);
    float inv = rsqrtf(fmaxf(s, 1e-30f));
    __half2 a0 = __floats2half2_rn(v0.x * inv, v0.y * inv);
    __half2 a1 = __floats2half2_rn(v0.z * inv, v0.w * inv);
    __half2 b0 = __floats2half2_rn(v1.x * inv, v1.y * inv);
    __half2 b1 = __floats2half2_rn(v1.z * inv, v1.w * inv);
    uint2* dst = (uint2*)(g_xnh + (size_t)row * DD);
    uint2 oa; oa.x = *(uint32_t*)&a0; oa.y = *(uint32_t*)&a1;
    uint2 ob; ob.x = *(uint32_t*)&b0; ob.y = *(uint32_t*)&b1;
    dst[lane] = oa;
    dst[lane + 32] = ob;
}

__global__ __launch_bounds__(128) void k_gate(const float* __restrict__ x,
                                              float* __restrict__ out)
{
    size_t row = blockIdx.x;
    int d2 = threadIdx.x * 2;
    const __half* gi = g_gi + row * G3;
    const __half* gh = g_gh + row * G3;
    __half2 ir = *(const __half2*)(gi + d2);
    __half2 hr = *(const __half2*)(gh + d2);
    __half2 iz = *(const __half2*)(gi + DD + d2);
    __half2 hz = *(const __half2*)(gh + DD + d2);
    __half2 in_ = *(const __half2*)(gi + 2 * DD + d2);
    __half2 hn = *(const __half2*)(gh + 2 * DD + d2);
    float2 xv = *(const float2*)(x + row * DD + d2);
    float r0 = 1.f / (1.f + __expf(-(__low2float(ir) + __low2float(hr))));
    float r1 = 1.f / (1.f + __expf(-(__high2float(ir) + __high2float(hr))));
    float z0 = 1.f / (1.f + __expf(-(__low2float(iz) + __low2float(hz))));
    float z1 = 1.f / (1.f + __expf(-(__high2float(iz) + __high2float(hz))));
    float n0 = tanhf(__low2float(in_) + r0 * __low2float(hn));
    float n1 = tanhf(__high2float(in_) + r1 * __high2float(hn));
    float2 o;
    o.x = (1.f - z0) * n0 + z0 * xv.x;
    o.y = (1.f - z1) * n1 + z1 * xv.y;
    *(float2*)(out + row * DD + d2) = o;
}

// ---------------------------------------------------------------------------
// Launch — parallel-DAG graph: pack (sB), norm (sN), gh (sC) overlapped.
// ---------------------------------------------------------------------------
extern "C" void kernel_launch(void* const* d_in, const int* in_sizes, int n_in,
                              void* d_out, int out_size)
{
    const int*   adj  = (const int*)  d_in[0];
    const float* x    = (const float*)d_in[1];
    const float* xt   = (const float*)d_in[2];
    const float* W    = (const float*)d_in[3];
    const float* W_ih = (const float*)d_in[4];
    const float* W_hh = (const float*)d_in[5];
    const float* b_ih = (const float*)d_in[6];
    const float* b_hh = (const float*)d_in[7];
    float* out = (float*)d_out;

    static bool init_done = []() {
        cudaFuncSetAttribute(gemm_h<0>, cudaFuncAttributeMaxDynamicSharedMemorySize, SMEM_TOTAL);
        cudaFuncSetAttribute(gemm_h<3>, cudaFuncAttributeMaxDynamicSharedMemorySize, SMEM_TOTAL);
        cudaFuncSetAttribute(k_attn,    cudaFuncAttributeMaxDynamicSharedMemorySize, SMEM_ATT);
        return true;
    }();
    (void)init_done;

    static cudaStream_t sB = []() {
        cudaStream_t s; cudaStreamCreateWithFlags(&s, cudaStreamNonBlocking); return s;
    }();
    static cudaStream_t sC = []() {
        cudaStream_t s; cudaStreamCreateWithFlags(&s, cudaStreamNonBlocking); return s;
    }();
    static cudaStream_t sN = []() {
        cudaStream_t s; cudaStreamCreateWithFlags(&s, cudaStreamNonBlocking); return s;
    }();
    static cudaEvent_t e0 = []() {
        cudaEvent_t e; cudaEventCreateWithFlags(&e, cudaEventDisableTiming); return e;
    }();
    static cudaEvent_t e1 = []() {
        cudaEvent_t e; cudaEventCreateWithFlags(&e, cudaEventDisableTiming); return e;
    }();
    static cudaEvent_t eB = []() {
        cudaEvent_t e; cudaEventCreateWithFlags(&e, cudaEventDisableTiming); return e;
    }();
    static cudaEvent_t eC = []() {
        cudaEvent_t e; cudaEventCreateWithFlags(&e, cudaEventDisableTiming); return e;
    }();
    static cudaEvent_t eN = []() {
        cudaEvent_t e; cudaEventCreateWithFlags(&e, cudaEventDisableTiming); return e;
    }();

    __half* xh  = nullptr; cudaGetSymbolAddress((void**)&xh,  g_xh);
    __half* xnh = nullptr; cudaGetSymbolAddress((void**)&xnh, g_xnh);
    __half* W16 = nullptr; cudaGetSymbolAddress((void**)&W16, g_W16);
    __half* Wih = nullptr; cudaGetSymbolAddress((void**)&Wih, g_Wihh);
    __half* Whh = nullptr; cudaGetSymbolAddress((void**)&Whh, g_Whhh);
    __half* WhO = nullptr; cudaGetSymbolAddress((void**)&WhO, g_WhO);
    __half* go  = nullptr; cudaGetSymbolAddress((void**)&go,  g_go);
    __half* gi  = nullptr; cudaGetSymbolAddress((void**)&gi,  g_gi);
    __half* gh  = nullptr; cudaGetSymbolAddress((void**)&gh,  g_gh);
    uint32_t* bits = nullptr; cudaGetSymbolAddress((void**)&bits, g_adjbits);

    // fork at t0: pack (adj only) and norm (xt only)
    cudaEventRecord(e0, 0);
    cudaStreamWaitEvent(sB, e0, 0);
    k_pack<<<MT / 8, 256, 0, sB>>>(adj);
    cudaEventRecord(eB, sB);
    cudaStreamWaitEvent(sN, e0, 0);
    k_norm<<<MT / 8, 256, 0, sN>>>(xt);
    cudaEventRecord(eN, sN);

    k_conv<<<(N4_TOT + 255) / 256, 256>>>(x, W, W_ih, W_hh);

    // fork C: gh = x @ W_hh^T + b_hh (needs conv only)
    cudaEventRecord(e1, 0);
    cudaStreamWaitEvent(sC, e1, 0);
    gemm_h<3><<<dim3(G3 / 128, MT / 128, 1), 256, SMEM_TOTAL, sC>>>(
        xh, Whh, gh, b_hh, DD, DD, DD, G3);
    cudaEventRecord(eC, sC);

    // main: Wh gemm, then attention (joins pack + norm)
    gemm_h<0><<<dim3(DD / 128, MT / 128, 1), 256, SMEM_TOTAL>>>(
        xh, W16, WhO, nullptr, DD, DD, DD, DD);
    cudaStreamWaitEvent(0, eB, 0);
    cudaStreamWaitEvent(0, eN, 0);
    k_attn<<<dim3(NN / 128, BATCH), 256, SMEM_ATT>>>(xnh, WhO, bits, go);

    gemm_h<3><<<dim3(G3 / 128, MT / 128, 1), 256, SMEM_TOTAL>>>(
        go, Wih, gi, b_ih, DD, DD, DD, G3);

    cudaStreamWaitEvent(0, eC, 0);
    k_gate<<<MT, 128>>>(x, out);
}